// round 14
// baseline (speedup 1.0000x reference)
#include <cuda_runtime.h>
#include <cstdint>

// ---------------------------------------------------------------------------
// BaseGCN round 8: launch diet. 13 kernels -> 8 kernels + 2 memsets:
//  - k_zero -> memsets + init folded into k_count's extra block (also head)
//  - k_scan2 deleted (redundant in-block scan of 98 bsums in k_scanf)
//  - k_fillcsr + k_permfill merged (redundant in-block hist scan)
//  - k_finish folded into k_z4pool via last-block ticket
// Compute path identical to round 7 (degree-sorted warp-fused layers).
// ---------------------------------------------------------------------------

#define NMAX 100352
#define EMAX 1600000
#define SCAN_BLK 1024

__device__ float g_dinv[NMAX];
__device__ int   g_deg [NMAX];
__device__ int   g_fill[NMAX];
__device__ int   g_rowptr[NMAX + 1];
__device__ int   g_bsums[256];
__device__ int   g_hist[256];
__device__ int   g_hfill[256];
__device__ int   g_perm[NMAX];
__device__ int   g_col  [EMAX];
__device__ int   g_counter[1];
__device__ float g_xs[(size_t)NMAX * 8];
__device__ float g_ha[(size_t)NMAX * 64];
__device__ float g_hb[(size_t)NMAX * 64];
__device__ float g_hp[(size_t)NMAX * 4];
__device__ float g_accum[64 * 4];
__device__ float g_Wc[64 * 4];
__device__ float g_bc[4];

static inline int cdiv(long a, long b) { return (int)((a + b - 1) / b); }

// ---------------- count (+ init small arrays + head precompose) ----------------
__global__ void k_count(const int* __restrict__ dst, int* __restrict__ deg, int e,
                        int* __restrict__ hist, int* __restrict__ hfill,
                        float* __restrict__ accum, int* __restrict__ counter,
                        const float* __restrict__ W4, const float* __restrict__ b4,
                        const float* __restrict__ Wlin, const float* __restrict__ blin,
                        float* __restrict__ Wc, float* __restrict__ bc) {
    if (blockIdx.x == gridDim.x - 1) {
        int t = threadIdx.x;
        hist[t] = 0; hfill[t] = 0; accum[t] = 0.f;
        if (t == 0) counter[0] = 0;
        // head precompose: Wc = W4 @ Wlin (64x128 @ 128x4), bc = b4 @ Wlin + blin
        int i = t >> 2, c = t & 3;
        float s = 0.f;
#pragma unroll 8
        for (int k = 0; k < 128; k++)
            s += __ldg(&W4[i * 128 + k]) * __ldg(&Wlin[k * 4 + c]);
        Wc[i * 4 + c] = s;
        if (i == 0) {
            float b = __ldg(&blin[c]);
#pragma unroll 8
            for (int k = 0; k < 128; k++)
                b += __ldg(&b4[k]) * __ldg(&Wlin[k * 4 + c]);
            bc[c] = b;
        }
        return;
    }
    int i = blockIdx.x * blockDim.x + threadIdx.x;
    if (i < e) atomicAdd(&deg[dst[i]], 1);
}

// scan deg -> rowptr (block-local), bsums; dinv; block-aggregated degree hist.
__global__ void k_scan1(const int* __restrict__ deg, int* __restrict__ rowptr,
                        int* __restrict__ bsums, float* __restrict__ dinv,
                        int* __restrict__ hist, int n) {
    __shared__ int sm[SCAN_BLK];
    __shared__ int hist_s[256];
    if (threadIdx.x < 256) hist_s[threadIdx.x] = 0;
    int i = blockIdx.x * SCAN_BLK + threadIdx.x;
    int v = (i < n) ? deg[i] : 0;
    if (i < n) dinv[i] = rsqrtf((float)v + 1.0f);
    sm[threadIdx.x] = v;
    __syncthreads();
    if (i < n) atomicAdd(&hist_s[v < 255 ? v : 255], 1);
#pragma unroll
    for (int off = 1; off < SCAN_BLK; off <<= 1) {
        int t = (threadIdx.x >= off) ? sm[threadIdx.x - off] : 0;
        __syncthreads();
        sm[threadIdx.x] += t;
        __syncthreads();
    }
    if (i < n) rowptr[i] = sm[threadIdx.x] - v;
    if (threadIdx.x == SCAN_BLK - 1) bsums[blockIdx.x] = sm[SCAN_BLK - 1];
    __syncthreads();
    if (threadIdx.x < 256 && hist_s[threadIdx.x])
        atomicAdd(&hist[threadIdx.x], hist_s[threadIdx.x]);
}

// finalize rowptr: each block redundantly ex-scans bsums (nscan<=256) in smem;
// also prescale x -> xs.
__global__ void k_scanf(int* __restrict__ rowptr, const int* __restrict__ bsums,
                        int nscan, const float* __restrict__ x,
                        const float* __restrict__ dinv, float* __restrict__ xs,
                        int n, int e) {
    __shared__ int sm[256];
    __shared__ int ex[256];
    int t = threadIdx.x;
    int v = (t < nscan) ? __ldg(&bsums[t]) : 0;
    sm[t] = v;
    __syncthreads();
#pragma unroll
    for (int off = 1; off < 256; off <<= 1) {
        int tmp = (t >= off) ? sm[t - off] : 0;
        __syncthreads();
        sm[t] += tmp;
        __syncthreads();
    }
    ex[t] = sm[t] - v;
    __syncthreads();

    int i = blockIdx.x * 256 + t;
    if (i < n) {
        rowptr[i] += ex[i / SCAN_BLK];
        float d = __ldg(&dinv[i]);
        const float4* x4 = reinterpret_cast<const float4*>(x) + (size_t)i * 2;
        float4* s4 = reinterpret_cast<float4*>(xs) + (size_t)i * 2;
        float4 a = __ldg(x4), b = __ldg(x4 + 1);
        a.x *= d; a.y *= d; a.z *= d; a.w *= d;
        b.x *= d; b.y *= d; b.z *= d; b.w *= d;
        s4[0] = a; s4[1] = b;
    }
    if (i == n) rowptr[n] = e;
}

// merged CSR fill + degree-sorted perm fill.
__global__ void k_fillperm(const int* __restrict__ src, const int* __restrict__ dst,
                           const int* __restrict__ rowptr, int* __restrict__ fill,
                           int* __restrict__ col, int e,
                           const int* __restrict__ deg, const int* __restrict__ hist,
                           int* __restrict__ hfill, int* __restrict__ perm, int n) {
    long i = (long)blockIdx.x * 256 + threadIdx.x;
    if (i < e) {
        int d = dst[i];
        int pos = __ldg(&rowptr[d]) + atomicAdd(&fill[d], 1);
        col[pos] = src[i];
    }
    // perm part: only blocks covering node range
    if ((long)blockIdx.x * 256 < n) {
        __shared__ int hsc[256];
        __shared__ int hbase_s[256];
        __shared__ int sbins[256];
        __shared__ int sbase[256];
        __shared__ int scnt[256];
        int t = threadIdx.x;
        int h = __ldg(&hist[t]);
        hsc[t] = h;
        __syncthreads();
#pragma unroll
        for (int off = 1; off < 256; off <<= 1) {
            int tmp = (t >= off) ? hsc[t - off] : 0;
            __syncthreads();
            hsc[t] += tmp;
            __syncthreads();
        }
        hbase_s[t] = hsc[t] - h;

        int b = -1;
        if (i < n) { int d = __ldg(&deg[i]); b = d < 255 ? d : 255; }
        sbins[t] = b;
        scnt[t] = 0;
        __syncthreads();
        if (b >= 0) atomicAdd(&scnt[b], 1);
        __syncthreads();
        if (scnt[t] > 0)
            sbase[t] = atomicAdd(&hfill[t], scnt[t]);
        __syncthreads();
        if (b >= 0) {
            int rank = 0;
            for (int j = 0; j < t; j++) rank += (sbins[j] == b);
            perm[hbase_s[b] + sbase[b] + rank] = (int)i;
        }
    }
}

// ---------------- warp-fused agg + shuffle GEMM + PReLU + prescale ----------
template<int FIN, int FOUT, bool PROJ>
__global__ void __launch_bounds__(256)
k_wlayer(const int* __restrict__ rowptr, const int* __restrict__ col,
         const int* __restrict__ perm,
         const float* __restrict__ hs, const float* __restrict__ dinv,
         const float* __restrict__ W, const float* __restrict__ bias,
         const float* __restrict__ aP, float* __restrict__ out,
         const float* __restrict__ Wc, float* __restrict__ hp, int n) {
    constexpr int TPE = FIN / 4;
    constexpr int NPB = 256 / TPE;
    constexpr int CPL = FOUT / TPE;
    static_assert(CPL == 8, "expect 8 cols/lane");

    __shared__ float Ws[FIN * FOUT];
    __shared__ float bs[FOUT];
    __shared__ float Wcs[PROJ ? FOUT * 4 : 1];
    for (int i = threadIdx.x; i < FIN * FOUT; i += 256) Ws[i] = __ldg(&W[i]);
    if (threadIdx.x < FOUT) bs[threadIdx.x] = __ldg(&bias[threadIdx.x]);
    if (PROJ) {
        for (int i = threadIdx.x; i < FOUT * 4; i += 256) Wcs[i] = __ldg(&Wc[i]);
    }
    float a = __ldg(aP);
    __syncthreads();

    int group = threadIdx.x / TPE;
    int lane  = threadIdx.x % TPE;
    int idx   = blockIdx.x * NPB + group;
    bool live = (idx < n);
    int idx_c = live ? idx : (n - 1);
    int node  = __ldg(&perm[idx_c]);           // degree-sorted node id

    int beg = __ldg(&rowptr[node]);
    int end = __ldg(&rowptr[node + 1]);
    const float4* h4 = reinterpret_cast<const float4*>(hs);
    float4 acc = __ldg(h4 + (size_t)node * TPE + lane);   // self (pre-scaled)
    int p = beg;
    for (; p + 4 <= end; p += 4) {
        int s0 = __ldg(&col[p + 0]);
        int s1 = __ldg(&col[p + 1]);
        int s2 = __ldg(&col[p + 2]);
        int s3 = __ldg(&col[p + 3]);
        float4 v0 = __ldg(h4 + (size_t)s0 * TPE + lane);
        float4 v1 = __ldg(h4 + (size_t)s1 * TPE + lane);
        float4 v2 = __ldg(h4 + (size_t)s2 * TPE + lane);
        float4 v3 = __ldg(h4 + (size_t)s3 * TPE + lane);
        acc.x += v0.x + v1.x + v2.x + v3.x;
        acc.y += v0.y + v1.y + v2.y + v3.y;
        acc.z += v0.z + v1.z + v2.z + v3.z;
        acc.w += v0.w + v1.w + v2.w + v3.w;
    }
    for (; p < end; p++) {
        int s = __ldg(&col[p]);
        float4 v = __ldg(h4 + (size_t)s * TPE + lane);
        acc.x += v.x; acc.y += v.y; acc.z += v.z; acc.w += v.w;
    }
    float dn = __ldg(&dinv[node]);
    float za[4] = {acc.x * dn, acc.y * dn, acc.z * dn, acc.w * dn};

    int lane32 = threadIdx.x & 31;
    int base   = lane32 & ~(TPE - 1);
    int c0 = lane * CPL;
    float4 o0 = *reinterpret_cast<const float4*>(&bs[c0]);
    float4 o1 = *reinterpret_cast<const float4*>(&bs[c0 + 4]);
#pragma unroll
    for (int k4 = 0; k4 < TPE; k4++) {
#pragma unroll
        for (int j = 0; j < 4; j++) {
            float zk = __shfl_sync(0xffffffffu, za[j], base + k4);
            int k = k4 * 4 + j;
            float4 wa = *reinterpret_cast<const float4*>(&Ws[k * FOUT + c0]);
            float4 wb = *reinterpret_cast<const float4*>(&Ws[k * FOUT + c0 + 4]);
            o0.x += zk * wa.x; o0.y += zk * wa.y; o0.z += zk * wa.z; o0.w += zk * wa.w;
            o1.x += zk * wb.x; o1.y += zk * wb.y; o1.z += zk * wb.z; o1.w += zk * wb.w;
        }
    }
    o0.x = o0.x >= 0.f ? o0.x : a * o0.x;
    o0.y = o0.y >= 0.f ? o0.y : a * o0.y;
    o0.z = o0.z >= 0.f ? o0.z : a * o0.z;
    o0.w = o0.w >= 0.f ? o0.w : a * o0.w;
    o1.x = o1.x >= 0.f ? o1.x : a * o1.x;
    o1.y = o1.y >= 0.f ? o1.y : a * o1.y;
    o1.z = o1.z >= 0.f ? o1.z : a * o1.z;
    o1.w = o1.w >= 0.f ? o1.w : a * o1.w;
    o0.x *= dn; o0.y *= dn; o0.z *= dn; o0.w *= dn;
    o1.x *= dn; o1.y *= dn; o1.z *= dn; o1.w *= dn;
    if (live) {
        float4* orow = reinterpret_cast<float4*>(out + (size_t)node * FOUT + c0);
        orow[0] = o0;
        orow[1] = o1;
    }

    if (PROJ) {
        float pj[4] = {0.f, 0.f, 0.f, 0.f};
        float hvals[8] = {o0.x, o0.y, o0.z, o0.w, o1.x, o1.y, o1.z, o1.w};
#pragma unroll
        for (int j = 0; j < 8; j++) {
            float4 w = *reinterpret_cast<const float4*>(&Wcs[(c0 + j) * 4]);
            pj[0] += hvals[j] * w.x; pj[1] += hvals[j] * w.y;
            pj[2] += hvals[j] * w.z; pj[3] += hvals[j] * w.w;
        }
#pragma unroll
        for (int off = TPE / 2; off > 0; off >>= 1) {
#pragma unroll
            for (int j = 0; j < 4; j++)
                pj[j] += __shfl_xor_sync(0xffffffffu, pj[j], off);
        }
        if (live && lane == 0) {
            float4 r = {pj[0], pj[1], pj[2], pj[3]};
            reinterpret_cast<float4*>(hp)[node] = r;
        }
    }
}

// ---------------- fused layer-4 agg (4-wide) + pooling + last-block finish --
__device__ __forceinline__ int lower_bound_i(const int* b, int n, int v) {
    int lo = 0, hi = n;
    while (lo < hi) {
        int m = (lo + hi) >> 1;
        if (__ldg(&b[m]) < v) lo = m + 1; else hi = m;
    }
    return lo;
}

__global__ void __launch_bounds__(256)
k_z4pool(const int* __restrict__ rowptr, const int* __restrict__ col,
         const int* __restrict__ perm,
         const float* __restrict__ hp, const float* __restrict__ dinv,
         const int* __restrict__ batch, float* __restrict__ accum,
         int* __restrict__ counter, const float* __restrict__ bc,
         float* __restrict__ out, int n, int G) {
    __shared__ float acc_s[64 * 4];
    if (threadIdx.x < 256) acc_s[threadIdx.x] = 0.f;
    __syncthreads();

    int i = blockIdx.x * blockDim.x + threadIdx.x;
    if (i < n) {
        int node = __ldg(&perm[i]);
        const float4* hp4 = reinterpret_cast<const float4*>(hp);
        float4 acc = __ldg(hp4 + node);
        int beg = __ldg(&rowptr[node]);
        int end = __ldg(&rowptr[node + 1]);
        int p = beg;
        for (; p + 4 <= end; p += 4) {
            int s0 = __ldg(&col[p + 0]);
            int s1 = __ldg(&col[p + 1]);
            int s2 = __ldg(&col[p + 2]);
            int s3 = __ldg(&col[p + 3]);
            float4 v0 = __ldg(hp4 + s0);
            float4 v1 = __ldg(hp4 + s1);
            float4 v2 = __ldg(hp4 + s2);
            float4 v3 = __ldg(hp4 + s3);
            acc.x += v0.x + v1.x + v2.x + v3.x;
            acc.y += v0.y + v1.y + v2.y + v3.y;
            acc.z += v0.z + v1.z + v2.z + v3.z;
            acc.w += v0.w + v1.w + v2.w + v3.w;
        }
        for (; p < end; p++) {
            int s = __ldg(&col[p]);
            float4 v = __ldg(hp4 + s);
            acc.x += v.x; acc.y += v.y; acc.z += v.z; acc.w += v.w;
        }
        float d = __ldg(&dinv[node]);
        int g = __ldg(&batch[node]);
        atomicAdd(&acc_s[g * 4 + 0], acc.x * d);
        atomicAdd(&acc_s[g * 4 + 1], acc.y * d);
        atomicAdd(&acc_s[g * 4 + 2], acc.z * d);
        atomicAdd(&acc_s[g * 4 + 3], acc.w * d);
    }
    __syncthreads();
    if (threadIdx.x < 256) {
        float v = acc_s[threadIdx.x];
        if (v != 0.f) atomicAdd(&accum[threadIdx.x], v);
    }
    // last-block finish
    __threadfence();
    __shared__ int slast;
    if (threadIdx.x == 0)
        slast = (atomicAdd(counter, 1) == (int)gridDim.x - 1);
    __syncthreads();
    if (slast) {
        int t = threadIdx.x;
        int g = t >> 2, c = t & 3;
        if (g < G) {
            int start = lower_bound_i(batch, n, g);
            int end   = lower_bound_i(batch, n, g + 1);
            int cnt = end - start;
            float denom = (float)(cnt > 1 ? cnt : 1);
            float av = atomicAdd(&accum[t], 0.0f);   // coherent L2 read
            out[g * 4 + c] = av / denom + __ldg(&bc[c]);
        }
    }
}

// ---------------------------------------------------------------------------
extern "C" void kernel_launch(void* const* d_in, const int* in_sizes, int n_in,
                              void* d_out, int out_size) {
    const float* x    = (const float*)d_in[0];
    const int* esrc   = (const int*)d_in[1];
    const int* edst   = (const int*)d_in[2];
    const int* batch  = (const int*)d_in[3];
    const float* W1   = (const float*)d_in[4];
    const float* b1   = (const float*)d_in[5];
    const float* W2   = (const float*)d_in[6];
    const float* b2   = (const float*)d_in[7];
    const float* W3   = (const float*)d_in[8];
    const float* b3   = (const float*)d_in[9];
    const float* W4   = (const float*)d_in[10];
    const float* b4   = (const float*)d_in[11];
    const float* a1   = (const float*)d_in[12];
    const float* a2   = (const float*)d_in[13];
    const float* a3   = (const float*)d_in[14];
    const float* Wlin = (const float*)d_in[15];
    const float* blin = (const float*)d_in[16];
    float* out = (float*)d_out;

    int n = in_sizes[0] / 8;
    int e = in_sizes[1];
    int G = out_size / 4;

    float *dinv, *xs, *ha, *hb, *hp, *accum, *Wc, *bc;
    int *deg, *fill, *rowptr, *bsums, *col, *hist, *hfill, *perm, *counter;
    cudaGetSymbolAddress((void**)&dinv,    g_dinv);
    cudaGetSymbolAddress((void**)&deg,     g_deg);
    cudaGetSymbolAddress((void**)&fill,    g_fill);
    cudaGetSymbolAddress((void**)&rowptr,  g_rowptr);
    cudaGetSymbolAddress((void**)&bsums,   g_bsums);
    cudaGetSymbolAddress((void**)&hist,    g_hist);
    cudaGetSymbolAddress((void**)&hfill,   g_hfill);
    cudaGetSymbolAddress((void**)&perm,    g_perm);
    cudaGetSymbolAddress((void**)&col,     g_col);
    cudaGetSymbolAddress((void**)&counter, g_counter);
    cudaGetSymbolAddress((void**)&xs,      g_xs);
    cudaGetSymbolAddress((void**)&ha,      g_ha);
    cudaGetSymbolAddress((void**)&hb,      g_hb);
    cudaGetSymbolAddress((void**)&hp,      g_hp);
    cudaGetSymbolAddress((void**)&accum,   g_accum);
    cudaGetSymbolAddress((void**)&Wc,      g_Wc);
    cudaGetSymbolAddress((void**)&bc,      g_bc);

    const int T = 256;
    int nscan = cdiv(n, SCAN_BLK);

    cudaMemsetAsync(deg,  0, (size_t)n * sizeof(int));
    cudaMemsetAsync(fill, 0, (size_t)n * sizeof(int));

    k_count<<<cdiv(e, T) + 1, T>>>(edst, deg, e, hist, hfill, accum, counter,
                                   W4, b4, Wlin, blin, Wc, bc);
    k_scan1<<<nscan, SCAN_BLK>>>(deg, rowptr, bsums, dinv, hist, n);
    k_scanf<<<cdiv(n + 1, T), T>>>(rowptr, bsums, nscan, x, dinv, xs, n, e);
    k_fillperm<<<cdiv(e, T), T>>>(esrc, edst, rowptr, fill, col, e,
                                  deg, hist, hfill, perm, n);

    // Layers 1-3: warp-fused agg + shuffle GEMM on degree-sorted nodes
    k_wlayer<8, 16, false><<<cdiv(n, 128), T>>>(rowptr, col, perm, xs, dinv, W1, b1, a1, ha, nullptr, nullptr, n);
    k_wlayer<16, 32, false><<<cdiv(n, 64), T>>>(rowptr, col, perm, ha, dinv, W2, b2, a2, hb, nullptr, nullptr, n);
    k_wlayer<32, 64, true> <<<cdiv(n, 32), T>>>(rowptr, col, perm, hb, dinv, W3, b3, a3, ha, Wc, hp, n);

    // Layer 4 (4-wide) + pooling + finish (last block)
    k_z4pool<<<cdiv(n, T), T>>>(rowptr, col, perm, hp, dinv, batch, accum,
                                counter, bc, out, n, G);
}

// round 15
// speedup vs baseline: 1.1389x; 1.1389x over previous
#include <cuda_runtime.h>
#include <cuda_fp16.h>
#include <cstdint>

// ---------------------------------------------------------------------------
// BaseGCN round 9:
//  - fp16 storage for activations (xs/ha/hb); all compute in fp32.
//    Halves the dominant random-gather sector traffic in layers 2-3.
//  - k_fillperm ranking via __match_any_sync (O(1) instead of O(255) loop).
//  - keeps: degree-sorted perm, warp-fused agg+shuffle GEMM, projected
//    layer-4 + fused pooling + last-block finish, composed head.
// ---------------------------------------------------------------------------

#define NMAX 100352
#define EMAX 1600000
#define SCAN_BLK 1024

__device__ float g_dinv[NMAX];
__device__ int   g_deg [NMAX];
__device__ int   g_fill[NMAX];
__device__ int   g_rowptr[NMAX + 1];
__device__ int   g_bsums[256];
__device__ int   g_hist[256];
__device__ int   g_hfill[256];
__device__ int   g_perm[NMAX];
__device__ int   g_col  [EMAX];
__device__ int   g_counter[1];
__device__ __align__(16) __half g_xs[(size_t)NMAX * 8];
__device__ __align__(16) __half g_ha[(size_t)NMAX * 64];
__device__ __align__(16) __half g_hb[(size_t)NMAX * 64];
__device__ float g_hp[(size_t)NMAX * 4];
__device__ float g_accum[64 * 4];
__device__ float g_Wc[64 * 4];
__device__ float g_bc[4];

static inline int cdiv(long a, long b) { return (int)((a + b - 1) / b); }

// ---------------- count (+ init small arrays + head precompose) -------------
__global__ void k_count(const int* __restrict__ dst, int* __restrict__ deg, int e,
                        int* __restrict__ hist, int* __restrict__ hfill,
                        float* __restrict__ accum, int* __restrict__ counter,
                        const float* __restrict__ W4, const float* __restrict__ b4,
                        const float* __restrict__ Wlin, const float* __restrict__ blin,
                        float* __restrict__ Wc, float* __restrict__ bc) {
    if (blockIdx.x == gridDim.x - 1) {
        int t = threadIdx.x;
        hist[t] = 0; hfill[t] = 0; accum[t] = 0.f;
        if (t == 0) counter[0] = 0;
        int i = t >> 2, c = t & 3;
        float s = 0.f;
#pragma unroll 8
        for (int k = 0; k < 128; k++)
            s += __ldg(&W4[i * 128 + k]) * __ldg(&Wlin[k * 4 + c]);
        Wc[i * 4 + c] = s;
        if (i == 0) {
            float b = __ldg(&blin[c]);
#pragma unroll 8
            for (int k = 0; k < 128; k++)
                b += __ldg(&b4[k]) * __ldg(&Wlin[k * 4 + c]);
            bc[c] = b;
        }
        return;
    }
    int i = blockIdx.x * blockDim.x + threadIdx.x;
    if (i < e) atomicAdd(&deg[dst[i]], 1);
}

// scan deg -> rowptr (block-local), bsums; dinv; block-aggregated degree hist.
__global__ void k_scan1(const int* __restrict__ deg, int* __restrict__ rowptr,
                        int* __restrict__ bsums, float* __restrict__ dinv,
                        int* __restrict__ hist, int n) {
    __shared__ int sm[SCAN_BLK];
    __shared__ int hist_s[256];
    if (threadIdx.x < 256) hist_s[threadIdx.x] = 0;
    int i = blockIdx.x * SCAN_BLK + threadIdx.x;
    int v = (i < n) ? deg[i] : 0;
    if (i < n) dinv[i] = rsqrtf((float)v + 1.0f);
    sm[threadIdx.x] = v;
    __syncthreads();
    if (i < n) atomicAdd(&hist_s[v < 255 ? v : 255], 1);
#pragma unroll
    for (int off = 1; off < SCAN_BLK; off <<= 1) {
        int t = (threadIdx.x >= off) ? sm[threadIdx.x - off] : 0;
        __syncthreads();
        sm[threadIdx.x] += t;
        __syncthreads();
    }
    if (i < n) rowptr[i] = sm[threadIdx.x] - v;
    if (threadIdx.x == SCAN_BLK - 1) bsums[blockIdx.x] = sm[SCAN_BLK - 1];
    __syncthreads();
    if (threadIdx.x < 256 && hist_s[threadIdx.x])
        atomicAdd(&hist[threadIdx.x], hist_s[threadIdx.x]);
}

// finalize rowptr (redundant in-block scan of bsums); prescale x -> xs (fp16)
__global__ void k_scanf(int* __restrict__ rowptr, const int* __restrict__ bsums,
                        int nscan, const float* __restrict__ x,
                        const float* __restrict__ dinv, __half* __restrict__ xs,
                        int n, int e) {
    __shared__ int sm[256];
    __shared__ int ex[256];
    int t = threadIdx.x;
    int v = (t < nscan) ? __ldg(&bsums[t]) : 0;
    sm[t] = v;
    __syncthreads();
#pragma unroll
    for (int off = 1; off < 256; off <<= 1) {
        int tmp = (t >= off) ? sm[t - off] : 0;
        __syncthreads();
        sm[t] += tmp;
        __syncthreads();
    }
    ex[t] = sm[t] - v;
    __syncthreads();

    int i = blockIdx.x * 256 + t;
    if (i < n) {
        rowptr[i] += ex[i / SCAN_BLK];
        float d = __ldg(&dinv[i]);
        const float4* x4 = reinterpret_cast<const float4*>(x) + (size_t)i * 2;
        float4 a = __ldg(x4), b = __ldg(x4 + 1);
        __half2 h[4];
        h[0] = __float22half2_rn(make_float2(a.x * d, a.y * d));
        h[1] = __float22half2_rn(make_float2(a.z * d, a.w * d));
        h[2] = __float22half2_rn(make_float2(b.x * d, b.y * d));
        h[3] = __float22half2_rn(make_float2(b.z * d, b.w * d));
        *reinterpret_cast<uint4*>(xs + (size_t)i * 8) = *reinterpret_cast<uint4*>(h);
    }
    if (i == n) rowptr[n] = e;
}

// merged CSR fill + degree-sorted perm (match_any ranking)
__global__ void k_fillperm(const int* __restrict__ src, const int* __restrict__ dst,
                           const int* __restrict__ rowptr, int* __restrict__ fill,
                           int* __restrict__ col, int e,
                           const int* __restrict__ deg, const int* __restrict__ hist,
                           int* __restrict__ hfill, int* __restrict__ perm, int n) {
    long i = (long)blockIdx.x * 256 + threadIdx.x;
    if (i < e) {
        int d = dst[i];
        int pos = __ldg(&rowptr[d]) + atomicAdd(&fill[d], 1);
        col[pos] = src[i];
    }
    if ((long)blockIdx.x * 256 < n) {
        __shared__ int hsc[256];
        __shared__ int hbase_s[256];
        __shared__ int wcnt[8 * 256];      // per-warp per-bin counts -> prefixes
        __shared__ int blockbase[256];
        int t = threadIdx.x;
        int warp = t >> 5;
        int lane32 = t & 31;

        int h = __ldg(&hist[t]);
        hsc[t] = h;
#pragma unroll
        for (int w = 0; w < 8; w++) wcnt[w * 256 + t] = 0;
        __syncthreads();
#pragma unroll
        for (int off = 1; off < 256; off <<= 1) {
            int tmp = (t >= off) ? hsc[t - off] : 0;
            __syncthreads();
            hsc[t] += tmp;
            __syncthreads();
        }
        hbase_s[t] = hsc[t] - h;

        int b = -1;
        if (i < n) { int d = __ldg(&deg[i]); b = d < 255 ? d : 255; }
        unsigned mask = __match_any_sync(0xffffffffu, b);
        int rank_w = __popc(mask & ((1u << lane32) - 1u));
        if (b >= 0 && rank_w == 0)
            wcnt[warp * 256 + b] = __popc(mask);
        __syncthreads();
        // per-bin prefix over 8 warps (thread t owns bin t)
        {
            int run = 0;
#pragma unroll
            for (int w = 0; w < 8; w++) {
                int c = wcnt[w * 256 + t];
                wcnt[w * 256 + t] = run;
                run += c;
            }
            if (run > 0) blockbase[t] = atomicAdd(&hfill[t], run);
        }
        __syncthreads();
        if (b >= 0)
            perm[hbase_s[b] + blockbase[b] + wcnt[warp * 256 + b] + rank_w] = (int)i;
    }
}

// ---------------- fp16-IO warp-fused agg + shuffle GEMM ---------------------
// TPE = FIN/8 lanes per node; each lane gathers 8 half cols (16B vector).
template<int FIN, int FOUT, bool PROJ>
__global__ void __launch_bounds__(256)
k_hlayer(const int* __restrict__ rowptr, const int* __restrict__ col,
         const int* __restrict__ perm,
         const __half* __restrict__ hs, const float* __restrict__ dinv,
         const float* __restrict__ W, const float* __restrict__ bias,
         const float* __restrict__ aP, __half* __restrict__ out,
         const float* __restrict__ Wc, float* __restrict__ hp, int n) {
    constexpr int TPE = (FIN / 8) > 0 ? (FIN / 8) : 1;
    constexpr int NPB = 256 / TPE;
    constexpr int CPL = FOUT / TPE;           // 16 for all layers
    static_assert(CPL == 16, "expect 16 cols/lane");

    __shared__ float Ws[FIN * FOUT];
    __shared__ float bs[FOUT];
    __shared__ float Wcs[PROJ ? FOUT * 4 : 1];
    for (int i = threadIdx.x; i < FIN * FOUT; i += 256) Ws[i] = __ldg(&W[i]);
    if (threadIdx.x < FOUT) bs[threadIdx.x] = __ldg(&bias[threadIdx.x]);
    if (PROJ) {
        for (int i = threadIdx.x; i < FOUT * 4; i += 256) Wcs[i] = __ldg(&Wc[i]);
    }
    float a = __ldg(aP);
    __syncthreads();

    int group = threadIdx.x / TPE;
    int lane  = threadIdx.x % TPE;
    int idx   = blockIdx.x * NPB + group;
    bool live = (idx < n);
    int idx_c = live ? idx : (n - 1);
    int node  = __ldg(&perm[idx_c]);

    int beg = __ldg(&rowptr[node]);
    int end = __ldg(&rowptr[node + 1]);
    const uint4* h4 = reinterpret_cast<const uint4*>(hs);   // 8 halves per uint4

    float accf[8];
    {
        uint4 v = __ldg(h4 + (size_t)node * TPE + lane);    // self
        const __half2* hh = reinterpret_cast<const __half2*>(&v);
#pragma unroll
        for (int q = 0; q < 4; q++) {
            float2 f = __half22float2(hh[q]);
            accf[2 * q] = f.x; accf[2 * q + 1] = f.y;
        }
    }
    int p = beg;
    for (; p + 4 <= end; p += 4) {
        int s0 = __ldg(&col[p + 0]);
        int s1 = __ldg(&col[p + 1]);
        int s2 = __ldg(&col[p + 2]);
        int s3 = __ldg(&col[p + 3]);
        uint4 v0 = __ldg(h4 + (size_t)s0 * TPE + lane);
        uint4 v1 = __ldg(h4 + (size_t)s1 * TPE + lane);
        uint4 v2 = __ldg(h4 + (size_t)s2 * TPE + lane);
        uint4 v3 = __ldg(h4 + (size_t)s3 * TPE + lane);
        const __half2* a0 = reinterpret_cast<const __half2*>(&v0);
        const __half2* a1 = reinterpret_cast<const __half2*>(&v1);
        const __half2* a2 = reinterpret_cast<const __half2*>(&v2);
        const __half2* a3 = reinterpret_cast<const __half2*>(&v3);
#pragma unroll
        for (int q = 0; q < 4; q++) {
            __half2 s01 = __hadd2(a0[q], a1[q]);
            __half2 s23 = __hadd2(a2[q], a3[q]);
            float2 f0 = __half22float2(s01);
            float2 f1 = __half22float2(s23);
            accf[2 * q]     += f0.x + f1.x;
            accf[2 * q + 1] += f0.y + f1.y;
        }
    }
    for (; p < end; p++) {
        int s = __ldg(&col[p]);
        uint4 v = __ldg(h4 + (size_t)s * TPE + lane);
        const __half2* hh = reinterpret_cast<const __half2*>(&v);
#pragma unroll
        for (int q = 0; q < 4; q++) {
            float2 f = __half22float2(hh[q]);
            accf[2 * q] += f.x; accf[2 * q + 1] += f.y;
        }
    }
    float dn = __ldg(&dinv[node]);
    float za[8];
#pragma unroll
    for (int j = 0; j < 8; j++) za[j] = accf[j] * dn;

    // shuffle GEMM: lane computes columns [lane*16, lane*16+16)
    int lane32 = threadIdx.x & 31;
    int base   = lane32 & ~(TPE - 1);
    int c0 = lane * CPL;
    float4 o[4];
#pragma unroll
    for (int q = 0; q < 4; q++)
        o[q] = *reinterpret_cast<const float4*>(&bs[c0 + 4 * q]);
#pragma unroll
    for (int k8 = 0; k8 < TPE; k8++) {
#pragma unroll
        for (int j = 0; j < 8; j++) {
            float zk = (TPE == 1) ? za[j] : __shfl_sync(0xffffffffu, za[j], base + k8);
            int k = k8 * 8 + j;
            const float4* wr = reinterpret_cast<const float4*>(&Ws[k * FOUT + c0]);
#pragma unroll
            for (int q = 0; q < 4; q++) {
                float4 w = wr[q];
                o[q].x += zk * w.x; o[q].y += zk * w.y;
                o[q].z += zk * w.z; o[q].w += zk * w.w;
            }
        }
    }
    // PReLU + prescale
#pragma unroll
    for (int q = 0; q < 4; q++) {
        o[q].x = (o[q].x >= 0.f ? o[q].x : a * o[q].x) * dn;
        o[q].y = (o[q].y >= 0.f ? o[q].y : a * o[q].y) * dn;
        o[q].z = (o[q].z >= 0.f ? o[q].z : a * o[q].z) * dn;
        o[q].w = (o[q].w >= 0.f ? o[q].w : a * o[q].w) * dn;
    }
    if (live) {
        __half2 hh[8];
#pragma unroll
        for (int q = 0; q < 4; q++) {
            hh[2 * q]     = __float22half2_rn(make_float2(o[q].x, o[q].y));
            hh[2 * q + 1] = __float22half2_rn(make_float2(o[q].z, o[q].w));
        }
        uint4* orow = reinterpret_cast<uint4*>(out + (size_t)node * FOUT + c0);
        orow[0] = reinterpret_cast<uint4*>(hh)[0];
        orow[1] = reinterpret_cast<uint4*>(hh)[1];
    }

    if (PROJ) {
        float pj[4] = {0.f, 0.f, 0.f, 0.f};
        const float* ov = &o[0].x;
#pragma unroll
        for (int j = 0; j < 16; j++) {
            float hv = ov[j];
            float4 w = *reinterpret_cast<const float4*>(&Wcs[(c0 + j) * 4]);
            pj[0] += hv * w.x; pj[1] += hv * w.y;
            pj[2] += hv * w.z; pj[3] += hv * w.w;
        }
#pragma unroll
        for (int off = TPE / 2; off > 0; off >>= 1) {
#pragma unroll
            for (int j = 0; j < 4; j++)
                pj[j] += __shfl_xor_sync(0xffffffffu, pj[j], off);
        }
        if (live && lane == 0) {
            float4 r = {pj[0], pj[1], pj[2], pj[3]};
            reinterpret_cast<float4*>(hp)[node] = r;
        }
    }
}

// ---------------- fused layer-4 agg (4-wide) + pooling + last-block finish --
__device__ __forceinline__ int lower_bound_i(const int* b, int n, int v) {
    int lo = 0, hi = n;
    while (lo < hi) {
        int m = (lo + hi) >> 1;
        if (__ldg(&b[m]) < v) lo = m + 1; else hi = m;
    }
    return lo;
}

__global__ void __launch_bounds__(256)
k_z4pool(const int* __restrict__ rowptr, const int* __restrict__ col,
         const int* __restrict__ perm,
         const float* __restrict__ hp, const float* __restrict__ dinv,
         const int* __restrict__ batch, float* __restrict__ accum,
         int* __restrict__ counter, const float* __restrict__ bc,
         float* __restrict__ out, int n, int G) {
    __shared__ float acc_s[64 * 4];
    if (threadIdx.x < 256) acc_s[threadIdx.x] = 0.f;
    __syncthreads();

    int i = blockIdx.x * blockDim.x + threadIdx.x;
    if (i < n) {
        int node = __ldg(&perm[i]);
        const float4* hp4 = reinterpret_cast<const float4*>(hp);
        float4 acc = __ldg(hp4 + node);
        int beg = __ldg(&rowptr[node]);
        int end = __ldg(&rowptr[node + 1]);
        int p = beg;
        for (; p + 4 <= end; p += 4) {
            int s0 = __ldg(&col[p + 0]);
            int s1 = __ldg(&col[p + 1]);
            int s2 = __ldg(&col[p + 2]);
            int s3 = __ldg(&col[p + 3]);
            float4 v0 = __ldg(hp4 + s0);
            float4 v1 = __ldg(hp4 + s1);
            float4 v2 = __ldg(hp4 + s2);
            float4 v3 = __ldg(hp4 + s3);
            acc.x += v0.x + v1.x + v2.x + v3.x;
            acc.y += v0.y + v1.y + v2.y + v3.y;
            acc.z += v0.z + v1.z + v2.z + v3.z;
            acc.w += v0.w + v1.w + v2.w + v3.w;
        }
        for (; p < end; p++) {
            int s = __ldg(&col[p]);
            float4 v = __ldg(hp4 + s);
            acc.x += v.x; acc.y += v.y; acc.z += v.z; acc.w += v.w;
        }
        float d = __ldg(&dinv[node]);
        int g = __ldg(&batch[node]);
        atomicAdd(&acc_s[g * 4 + 0], acc.x * d);
        atomicAdd(&acc_s[g * 4 + 1], acc.y * d);
        atomicAdd(&acc_s[g * 4 + 2], acc.z * d);
        atomicAdd(&acc_s[g * 4 + 3], acc.w * d);
    }
    __syncthreads();
    if (threadIdx.x < 256) {
        float v = acc_s[threadIdx.x];
        if (v != 0.f) atomicAdd(&accum[threadIdx.x], v);
    }
    __threadfence();
    __shared__ int slast;
    if (threadIdx.x == 0)
        slast = (atomicAdd(counter, 1) == (int)gridDim.x - 1);
    __syncthreads();
    if (slast) {
        int t = threadIdx.x;
        int g = t >> 2, c = t & 3;
        if (g < G) {
            int start = lower_bound_i(batch, n, g);
            int end   = lower_bound_i(batch, n, g + 1);
            int cnt = end - start;
            float denom = (float)(cnt > 1 ? cnt : 1);
            float av = atomicAdd(&accum[t], 0.0f);   // coherent read
            out[g * 4 + c] = av / denom + __ldg(&bc[c]);
        }
    }
}

// ---------------------------------------------------------------------------
extern "C" void kernel_launch(void* const* d_in, const int* in_sizes, int n_in,
                              void* d_out, int out_size) {
    const float* x    = (const float*)d_in[0];
    const int* esrc   = (const int*)d_in[1];
    const int* edst   = (const int*)d_in[2];
    const int* batch  = (const int*)d_in[3];
    const float* W1   = (const float*)d_in[4];
    const float* b1   = (const float*)d_in[5];
    const float* W2   = (const float*)d_in[6];
    const float* b2   = (const float*)d_in[7];
    const float* W3   = (const float*)d_in[8];
    const float* b3   = (const float*)d_in[9];
    const float* W4   = (const float*)d_in[10];
    const float* b4   = (const float*)d_in[11];
    const float* a1   = (const float*)d_in[12];
    const float* a2   = (const float*)d_in[13];
    const float* a3   = (const float*)d_in[14];
    const float* Wlin = (const float*)d_in[15];
    const float* blin = (const float*)d_in[16];
    float* out = (float*)d_out;

    int n = in_sizes[0] / 8;
    int e = in_sizes[1];
    int G = out_size / 4;

    float *dinv, *hp, *accum, *Wc, *bc;
    __half *xs, *ha, *hb;
    int *deg, *fill, *rowptr, *bsums, *col, *hist, *hfill, *perm, *counter;
    cudaGetSymbolAddress((void**)&dinv,    g_dinv);
    cudaGetSymbolAddress((void**)&deg,     g_deg);
    cudaGetSymbolAddress((void**)&fill,    g_fill);
    cudaGetSymbolAddress((void**)&rowptr,  g_rowptr);
    cudaGetSymbolAddress((void**)&bsums,   g_bsums);
    cudaGetSymbolAddress((void**)&hist,    g_hist);
    cudaGetSymbolAddress((void**)&hfill,   g_hfill);
    cudaGetSymbolAddress((void**)&perm,    g_perm);
    cudaGetSymbolAddress((void**)&col,     g_col);
    cudaGetSymbolAddress((void**)&counter, g_counter);
    cudaGetSymbolAddress((void**)&xs,      g_xs);
    cudaGetSymbolAddress((void**)&ha,      g_ha);
    cudaGetSymbolAddress((void**)&hb,      g_hb);
    cudaGetSymbolAddress((void**)&hp,      g_hp);
    cudaGetSymbolAddress((void**)&accum,   g_accum);
    cudaGetSymbolAddress((void**)&Wc,      g_Wc);
    cudaGetSymbolAddress((void**)&bc,      g_bc);

    const int T = 256;
    int nscan = cdiv(n, SCAN_BLK);

    cudaMemsetAsync(deg,  0, (size_t)n * sizeof(int));
    cudaMemsetAsync(fill, 0, (size_t)n * sizeof(int));

    k_count<<<cdiv(e, T) + 1, T>>>(edst, deg, e, hist, hfill, accum, counter,
                                   W4, b4, Wlin, blin, Wc, bc);
    k_scan1<<<nscan, SCAN_BLK>>>(deg, rowptr, bsums, dinv, hist, n);
    k_scanf<<<cdiv(n + 1, T), T>>>(rowptr, bsums, nscan, x, dinv, xs, n, e);
    k_fillperm<<<cdiv(e, T), T>>>(esrc, edst, rowptr, fill, col, e,
                                  deg, hist, hfill, perm, n);

    // Layers 1-3: fp16-IO warp-fused agg + shuffle GEMM (degree-sorted)
    k_hlayer<8, 16, false><<<cdiv(n, 256), T>>>(rowptr, col, perm, xs, dinv, W1, b1, a1, ha, nullptr, nullptr, n);
    k_hlayer<16, 32, false><<<cdiv(n, 128), T>>>(rowptr, col, perm, ha, dinv, W2, b2, a2, hb, nullptr, nullptr, n);
    k_hlayer<32, 64, true> <<<cdiv(n, 64), T>>>(rowptr, col, perm, hb, dinv, W3, b3, a3, ha, Wc, hp, n);

    // Layer 4 (4-wide) + pooling + finish
    k_z4pool<<<cdiv(n, T), T>>>(rowptr, col, perm, hp, dinv, batch, accum,
                                counter, bc, out, n, G);
}